// round 9
// baseline (speedup 1.0000x reference)
#include <cuda_runtime.h>
#include <cuda_bf16.h>
#include <mma.h>
#include <cstdint>

using namespace nvcuda;

// ---------------------------------------------------------------------------
// AdjGCN: 3-layer GCN forward.
//  - CSR-gather aggregation (no float atomics); CSR built on a forked stream;
//    edge payload packed as int2 (src, weight-bits).
//  - 128x128 GEMMs on wmma (HMMA), bf16x3 split for near-fp32 accuracy.
//  - Row-wise pipelining: gemm halves overlap agg halves on a side stream.
// ---------------------------------------------------------------------------

#define MAXN 100000
#define MAXNP 100096   // padded to multiple of 64 (wmma tail-block stores)
#define MAXE 1600000
#define DH   128
#define DO   40
#define LDX  136
#define LDW  136

__device__ float         g_bufA[(size_t)MAXNP * DH];
__device__ float         g_bufB[(size_t)MAXNP * DH];
__device__ int           g_idx64;
__device__ int           g_rowptr[MAXN + 1];
__device__ int           g_deg[MAXN];
__device__ int           g_fill[MAXN];
__device__ int2          g_epack[MAXE];     // (src, weight bits)
__device__ int           g_partials[128];
__device__ __nv_bfloat16 g_w1hi[128 * 128];
__device__ __nv_bfloat16 g_w1lo[128 * 128];
__device__ __nv_bfloat16 g_w2hi[128 * 128];
__device__ __nv_bfloat16 g_w2lo[128 * 128];

// ---------------------------------------------------------------------------
__device__ __forceinline__ void load_edge(const void* ei, int nedges, int e,
                                          int& s, int& d) {
    if (g_idx64) {
        const long long* p = (const long long*)ei;
        s = (int)p[e];
        d = (int)p[(size_t)nedges + e];
    } else {
        const int* p = (const int*)ei;
        s = p[e];
        d = p[(size_t)nedges + e];
    }
}

// ------------------------------ CSR build ---------------------------------
__global__ void deg_zero_kernel(int* __restrict__ deg, int n,
                                const void* ei, int n_nodes) {
    int i = blockIdx.x * blockDim.x + threadIdx.x;
    if (i < n) deg[i] = 0;
    if (blockIdx.x == 0 && threadIdx.x == 0) {
        const long long* p = (const long long*)ei;
        int ok64 = 1;
        for (int k = 0; k < 32; k++) {
            long long v = p[k];
            if (v < 0 || v >= n_nodes) { ok64 = 0; break; }
        }
        g_idx64 = ok64;
    }
}

__global__ void deg_count_kernel(const void* __restrict__ ei, int ne,
                                 int* __restrict__ deg) {
    int e = blockIdx.x * blockDim.x + threadIdx.x;
    if (e < ne) {
        int s, d;
        load_edge(ei, ne, e, s, d);
        atomicAdd(&deg[d], 1);
    }
}

__global__ void scan_block_kernel(const int* __restrict__ deg,
                                  int* __restrict__ rowptr,
                                  int* __restrict__ partials, int n) {
    __shared__ int sm[1024];
    const int tid = threadIdx.x;
    int i = blockIdx.x * 1024 + tid;
    int v = (i < n) ? deg[i] : 0;
    sm[tid] = v;
    __syncthreads();
#pragma unroll
    for (int o = 1; o < 1024; o <<= 1) {
        int t = (tid >= o) ? sm[tid - o] : 0;
        __syncthreads();
        sm[tid] += t;
        __syncthreads();
    }
    if (i < n) rowptr[i] = sm[tid] - v;
    if (tid == 1023) partials[blockIdx.x] = sm[1023];
}

__global__ void scan_partials_kernel(int* __restrict__ partials, int nb) {
    __shared__ int sm[128];
    const int tid = threadIdx.x;
    int v = (tid < nb) ? partials[tid] : 0;
    sm[tid] = v;
    __syncthreads();
#pragma unroll
    for (int o = 1; o < 128; o <<= 1) {
        int t = (tid >= o) ? sm[tid - o] : 0;
        __syncthreads();
        sm[tid] += t;
        __syncthreads();
    }
    if (tid < nb) partials[tid] = sm[tid] - v;
}

__global__ void scan_add_kernel(int* __restrict__ rowptr,
                                const int* __restrict__ partials,
                                int* __restrict__ fill, int n, int ne) {
    int i = blockIdx.x * blockDim.x + threadIdx.x;
    if (i < n) {
        int v = rowptr[i] + partials[i >> 10];
        rowptr[i] = v;
        fill[i] = v;
    }
    if (i == 0) rowptr[n] = ne;
}

__global__ void csr_fill_kernel(const void* __restrict__ ei,
                                const float* __restrict__ ew, int ne,
                                int* __restrict__ fill,
                                int2* __restrict__ epack) {
    int e = blockIdx.x * blockDim.x + threadIdx.x;
    if (e < ne) {
        int s, d;
        load_edge(ei, ne, e, s, d);
        int pos = atomicAdd(&fill[d], 1);
        epack[pos] = make_int2(s, __float_as_int(ew[e]));
    }
}

// ------------------- W prep: fp32 -> bf16 hi/lo (row-major) ----------------
__global__ void prep_w_kernel(const float* __restrict__ W,
                              __nv_bfloat16* __restrict__ hi,
                              __nv_bfloat16* __restrict__ lo) {
    int i = blockIdx.x * blockDim.x + threadIdx.x;
    if (i < 128 * 128) {
        float w = W[i];
        __nv_bfloat16 h = __float2bfloat16_rn(w);
        hi[i] = h;
        lo[i] = __float2bfloat16_rn(w - __bfloat162float(h));
    }
}

// -------------------- tensor-path GEMM (wmma bf16x3) -----------------------
__global__ void gemm128_tc_kernel(const float* __restrict__ X,
                                  const __nv_bfloat16* __restrict__ Whi,
                                  const __nv_bfloat16* __restrict__ Wlo,
                                  float* __restrict__ Y, int nrows) {
    extern __shared__ char smem[];
    __nv_bfloat16* xhi = (__nv_bfloat16*)smem;
    __nv_bfloat16* xlo = xhi + 64 * LDX;
    __nv_bfloat16* wh  = xlo + 64 * LDX;
    __nv_bfloat16* wl  = wh + 128 * LDW;
    const int tid = threadIdx.x;
    const int row0 = blockIdx.x * 64;

    {
        const float4* X4 = (const float4*)X;
#pragma unroll
        for (int i = tid; i < 64 * 32; i += 256) {
            int r = i >> 5, kq = i & 31;
            float4 v = (row0 + r < nrows)
                           ? X4[(size_t)(row0 + r) * 32 + kq]
                           : make_float4(0.f, 0.f, 0.f, 0.f);
            __nv_bfloat16 hx = __float2bfloat16_rn(v.x);
            __nv_bfloat16 hy = __float2bfloat16_rn(v.y);
            __nv_bfloat16 hz = __float2bfloat16_rn(v.z);
            __nv_bfloat16 hw = __float2bfloat16_rn(v.w);
            __nv_bfloat162 hp0 = __halves2bfloat162(hx, hy);
            __nv_bfloat162 hp1 = __halves2bfloat162(hz, hw);
            uint64_t hword = (uint64_t)(*(uint32_t*)&hp0)
                           | ((uint64_t)(*(uint32_t*)&hp1) << 32);
            *(uint64_t*)&xhi[r * LDX + kq * 4] = hword;
            __nv_bfloat162 lp0 = __halves2bfloat162(
                __float2bfloat16_rn(v.x - __bfloat162float(hx)),
                __float2bfloat16_rn(v.y - __bfloat162float(hy)));
            __nv_bfloat162 lp1 = __halves2bfloat162(
                __float2bfloat16_rn(v.z - __bfloat162float(hz)),
                __float2bfloat16_rn(v.w - __bfloat162float(hw)));
            uint64_t lword = (uint64_t)(*(uint32_t*)&lp0)
                           | ((uint64_t)(*(uint32_t*)&lp1) << 32);
            *(uint64_t*)&xlo[r * LDX + kq * 4] = lword;
        }
    }
    {
        const int4* h4 = (const int4*)Whi;
        const int4* l4 = (const int4*)Wlo;
#pragma unroll
        for (int i = tid; i < 2048; i += 256) {
            int k = i >> 4, seg = i & 15;
            *(int4*)&wh[k * LDW + seg * 8] = h4[i];
            *(int4*)&wl[k * LDW + seg * 8] = l4[i];
        }
    }
    __syncthreads();

    const int w  = tid >> 5;
    const int wr = w >> 2;
    const int wc = w & 3;

    wmma::fragment<wmma::accumulator, 16, 16, 16, float> acc[2][2];
#pragma unroll
    for (int i = 0; i < 2; i++)
#pragma unroll
        for (int j = 0; j < 2; j++) wmma::fill_fragment(acc[i][j], 0.f);

#pragma unroll
    for (int ks = 0; ks < 8; ks++) {
        const int k0 = ks * 16;
        wmma::fragment<wmma::matrix_a, 16, 16, 16, __nv_bfloat16,
                       wmma::row_major> ah[2], al[2];
        wmma::fragment<wmma::matrix_b, 16, 16, 16, __nv_bfloat16,
                       wmma::row_major> bh[2], bl[2];
#pragma unroll
        for (int i = 0; i < 2; i++) {
            wmma::load_matrix_sync(ah[i], &xhi[(wr * 32 + i * 16) * LDX + k0], LDX);
            wmma::load_matrix_sync(al[i], &xlo[(wr * 32 + i * 16) * LDX + k0], LDX);
        }
#pragma unroll
        for (int j = 0; j < 2; j++) {
            wmma::load_matrix_sync(bh[j], &wh[k0 * LDW + wc * 32 + j * 16], LDW);
            wmma::load_matrix_sync(bl[j], &wl[k0 * LDW + wc * 32 + j * 16], LDW);
        }
#pragma unroll
        for (int i = 0; i < 2; i++)
#pragma unroll
            for (int j = 0; j < 2; j++) {
                wmma::mma_sync(acc[i][j], ah[i], bh[j], acc[i][j]);
                wmma::mma_sync(acc[i][j], ah[i], bl[j], acc[i][j]);
                wmma::mma_sync(acc[i][j], al[i], bh[j], acc[i][j]);
            }
    }

#pragma unroll
    for (int i = 0; i < 2; i++)
#pragma unroll
        for (int j = 0; j < 2; j++) {
            int gr = row0 + wr * 32 + i * 16;
            int gc = wc * 32 + j * 16;
            wmma::store_matrix_sync(&Y[(size_t)gr * 128 + gc], acc[i][j],
                                    128, wmma::mem_row_major);
        }
}

// ------------------------- SIMT GEMM, D_OUT=40 ------------------------------
__global__ void gemm40_kernel(const float* __restrict__ X,
                              const float* __restrict__ W,
                              float* __restrict__ Y, int nrows) {
    extern __shared__ float sm[];
    float* Ws = sm;
    float* Xs = sm + 128 * DO;
    const int tid = threadIdx.x;

    for (int i = tid; i < 128 * DO; i += 320) Ws[i] = W[i];

    const int row0 = blockIdx.x * 64;
    const float4* X4 = (const float4*)X;
    float4* Xs4 = (float4*)Xs;
    for (int i = tid; i < 64 * 32; i += 320) {
        int gr = row0 + (i >> 5);
        Xs4[i] = (gr < nrows) ? X4[(size_t)gr * 32 + (i & 31)]
                              : make_float4(0.f, 0.f, 0.f, 0.f);
    }
    __syncthreads();

    const int c  = tid % DO;
    const int rg = tid / DO;
    float acc[8];
#pragma unroll
    for (int r = 0; r < 8; r++) acc[r] = 0.f;
    const float4* xb4 = (const float4*)(Xs + rg * 8 * 128);

#pragma unroll 4
    for (int k4 = 0; k4 < 32; k4++) {
        float w0 = Ws[(4 * k4 + 0) * DO + c];
        float w1 = Ws[(4 * k4 + 1) * DO + c];
        float w2 = Ws[(4 * k4 + 2) * DO + c];
        float w3 = Ws[(4 * k4 + 3) * DO + c];
#pragma unroll
        for (int r = 0; r < 8; r++) {
            float4 xv = xb4[r * 32 + k4];
            acc[r] += xv.x * w0 + xv.y * w1 + xv.z * w2 + xv.w * w3;
        }
    }
#pragma unroll
    for (int r = 0; r < 8; r++) {
        int gr = row0 + rg * 8 + r;
        if (gr < nrows) Y[(size_t)gr * DO + c] = acc[r];
    }
}

// ----------------------- CSR gather aggregation ----------------------------
// Node range [node0, node0+ncnt): one warp per node, fused bias+ReLU.
__global__ void agg128_kernel(const int* __restrict__ rowptr,
                              const int2* __restrict__ epack,
                              const float* __restrict__ H,
                              const float* __restrict__ bias,
                              float* __restrict__ Y, int node0, int ncnt) {
    int node = node0 + blockIdx.x * 8 + (threadIdx.x >> 5);
    if (node >= node0 + ncnt) return;
    const int lane = threadIdx.x & 31;
    int beg = rowptr[node];
    int end = rowptr[node + 1];

    float4 acc = make_float4(0.f, 0.f, 0.f, 0.f);
    int j = beg;
    for (; j + 3 < end; j += 4) {
        int2 e0 = epack[j];     int2 e1 = epack[j + 1];
        int2 e2 = epack[j + 2]; int2 e3 = epack[j + 3];
        float w0 = __int_as_float(e0.y), w1 = __int_as_float(e1.y);
        float w2 = __int_as_float(e2.y), w3 = __int_as_float(e3.y);
        float4 v0 = ((const float4*)(H + (size_t)e0.x * 128))[lane];
        float4 v1 = ((const float4*)(H + (size_t)e1.x * 128))[lane];
        float4 v2 = ((const float4*)(H + (size_t)e2.x * 128))[lane];
        float4 v3 = ((const float4*)(H + (size_t)e3.x * 128))[lane];
        acc.x += v0.x * w0 + v1.x * w1 + v2.x * w2 + v3.x * w3;
        acc.y += v0.y * w0 + v1.y * w1 + v2.y * w2 + v3.y * w3;
        acc.z += v0.z * w0 + v1.z * w1 + v2.z * w2 + v3.z * w3;
        acc.w += v0.w * w0 + v1.w * w1 + v2.w * w2 + v3.w * w3;
    }
    for (; j < end; j++) {
        int2 e = epack[j];
        float w = __int_as_float(e.y);
        float4 v = ((const float4*)(H + (size_t)e.x * 128))[lane];
        acc.x += v.x * w; acc.y += v.y * w; acc.z += v.z * w; acc.w += v.w * w;
    }

    float4 b = ((const float4*)bias)[lane];
    acc.x = fmaxf(acc.x + b.x, 0.f);
    acc.y = fmaxf(acc.y + b.y, 0.f);
    acc.z = fmaxf(acc.z + b.z, 0.f);
    acc.w = fmaxf(acc.w + b.w, 0.f);
    ((float4*)(Y + (size_t)node * 128))[lane] = acc;
}

__global__ void agg40_lsm_kernel(const int* __restrict__ rowptr,
                                 const int2* __restrict__ epack,
                                 const float* __restrict__ H,
                                 const float* __restrict__ b,
                                 float* __restrict__ out, int n) {
    int node = blockIdx.x * 8 + (threadIdx.x >> 5);
    if (node >= n) return;
    const int lane = threadIdx.x & 31;
    int beg = rowptr[node];
    int end = rowptr[node + 1];

    float a0 = 0.f, a1 = 0.f;
    int j = beg;
    for (; j + 1 < end; j += 2) {
        int2 e0 = epack[j]; int2 e1 = epack[j + 1];
        float w0 = __int_as_float(e0.y), w1 = __int_as_float(e1.y);
        const float* h0 = H + (size_t)e0.x * DO;
        const float* h1 = H + (size_t)e1.x * DO;
        a0 += h0[lane] * w0 + h1[lane] * w1;
        if (lane < 8) a1 += h0[32 + lane] * w0 + h1[32 + lane] * w1;
    }
    if (j < end) {
        int2 e = epack[j];
        float w = __int_as_float(e.y);
        const float* hs = H + (size_t)e.x * DO;
        a0 += hs[lane] * w;
        if (lane < 8) a1 += hs[32 + lane] * w;
    }

    float v0 = a0 + b[lane];
    float v1 = (lane < 8) ? (a1 + b[32 + lane]) : -1e30f;

    float m = fmaxf(v0, v1);
#pragma unroll
    for (int o = 16; o; o >>= 1) m = fmaxf(m, __shfl_xor_sync(0xffffffffu, m, o));

    float sum = __expf(v0 - m) + ((lane < 8) ? __expf(v1 - m) : 0.f);
#pragma unroll
    for (int o = 16; o; o >>= 1) sum += __shfl_xor_sync(0xffffffffu, sum, o);

    float lse = m + __logf(sum);
    out[(size_t)node * DO + lane] = v0 - lse;
    if (lane < 8) out[(size_t)node * DO + 32 + lane] = v1 - lse;
}

// ---------------------------------------------------------------------------
extern "C" void kernel_launch(void* const* d_in, const int* in_sizes, int n_in,
                              void* d_out, int out_size) {
    const float* x  = (const float*)d_in[0];
    const void*  ei = d_in[1];
    const float* ew = (const float*)d_in[2];
    const float* W1 = (const float*)d_in[3];
    const float* b1 = (const float*)d_in[4];
    const float* W2 = (const float*)d_in[5];
    const float* b2 = (const float*)d_in[6];
    const float* W3 = (const float*)d_in[7];
    const float* b3 = (const float*)d_in[8];
    float* out = (float*)d_out;

    const int n  = in_sizes[0] / DH;
    int ne = in_sizes[1] / 2;
    if (ne > MAXE) ne = MAXE;
    (void)n_in; (void)out_size;

    float *A, *B;
    int *rowptr, *deg, *fill, *partials;
    int2* epack;
    __nv_bfloat16 *w1hi, *w1lo, *w2hi, *w2lo;
    cudaGetSymbolAddress((void**)&A, g_bufA);
    cudaGetSymbolAddress((void**)&B, g_bufB);
    cudaGetSymbolAddress((void**)&rowptr, g_rowptr);
    cudaGetSymbolAddress((void**)&deg, g_deg);
    cudaGetSymbolAddress((void**)&fill, g_fill);
    cudaGetSymbolAddress((void**)&epack, g_epack);
    cudaGetSymbolAddress((void**)&partials, g_partials);
    cudaGetSymbolAddress((void**)&w1hi, g_w1hi);
    cudaGetSymbolAddress((void**)&w1lo, g_w1lo);
    cudaGetSymbolAddress((void**)&w2hi, g_w2hi);
    cudaGetSymbolAddress((void**)&w2lo, g_w2lo);

    const int SMEM_TC = (2 * 64 * LDX + 2 * 128 * LDW) * (int)sizeof(__nv_bfloat16);
    const int SMEM40  = (128 * DO + 64 * 128) * (int)sizeof(float);
    cudaFuncSetAttribute(gemm128_tc_kernel,
                         cudaFuncAttributeMaxDynamicSharedMemorySize, SMEM_TC);
    cudaFuncSetAttribute(gemm40_kernel,
                         cudaFuncAttributeMaxDynamicSharedMemorySize, SMEM40);

    // Node halves: h0 is a multiple of 64 (gemm tile) and 8 (agg warp-block).
    const int h0 = ((n / 2) + 63) & ~63;      // 50048 for n=100000
    const int h1 = n - h0;
    const int tcB_full  = (n + 63) / 64;
    const int tcB_h0    = (h0 + 63) / 64;
    const int tcB_h1    = (h1 + 63) / 64;
    const int aggB_h0   = (h0 + 7) / 8;
    const int aggB_h1   = (h1 + 7) / 8;
    const int aggB_full = (n + 7) / 8;
    const int scanBlocks = (n + 1023) / 1024;

    static cudaStream_t s2 = nullptr;
    static cudaEvent_t evFork = nullptr, evJoin = nullptr;
    static cudaEvent_t evA = nullptr, evB = nullptr, evC = nullptr, evD = nullptr;
    if (s2 == nullptr) {
        cudaStreamCreateWithFlags(&s2, cudaStreamNonBlocking);
        cudaEventCreateWithFlags(&evFork, cudaEventDisableTiming);
        cudaEventCreateWithFlags(&evJoin, cudaEventDisableTiming);
        cudaEventCreateWithFlags(&evA, cudaEventDisableTiming);
        cudaEventCreateWithFlags(&evB, cudaEventDisableTiming);
        cudaEventCreateWithFlags(&evC, cudaEventDisableTiming);
        cudaEventCreateWithFlags(&evD, cudaEventDisableTiming);
    }

    // ---- fork: CSR build on side stream ----
    cudaEventRecord(evFork, 0);
    cudaStreamWaitEvent(s2, evFork, 0);
    deg_zero_kernel<<<(n + 255) / 256, 256, 0, s2>>>(deg, n, ei, n);
    deg_count_kernel<<<(ne + 255) / 256, 256, 0, s2>>>(ei, ne, deg);
    scan_block_kernel<<<scanBlocks, 1024, 0, s2>>>(deg, rowptr, partials, n);
    scan_partials_kernel<<<1, 128, 0, s2>>>(partials, scanBlocks);
    scan_add_kernel<<<(n + 255) / 256, 256, 0, s2>>>(rowptr, partials, fill, n, ne);
    csr_fill_kernel<<<(ne + 255) / 256, 256, 0, s2>>>(ei, ew, ne, fill, epack);
    cudaEventRecord(evJoin, s2);

    // ---- main stream: W prep + layer-1 GEMM overlap CSR build ----
    prep_w_kernel<<<64, 256>>>(W1, w1hi, w1lo);
    prep_w_kernel<<<64, 256>>>(W2, w2hi, w2lo);
    gemm128_tc_kernel<<<tcB_full, 256, SMEM_TC>>>(x, w1hi, w1lo, A, n);

    // ---- join CSR ----
    cudaStreamWaitEvent(0, evJoin, 0);

    // ---- layer 1 agg (halves), layer 2 gemm pipelined on side stream ----
    agg128_kernel<<<aggB_h0, 256>>>(rowptr, epack, A, b1, B, 0, h0);
    cudaEventRecord(evA, 0);
    agg128_kernel<<<aggB_h1, 256>>>(rowptr, epack, A, b1, B, h0, h1);

    cudaStreamWaitEvent(s2, evA, 0);
    gemm128_tc_kernel<<<tcB_h0, 256, SMEM_TC, s2>>>(B, w2hi, w2lo, A, h0);
    cudaEventRecord(evB, s2);

    gemm128_tc_kernel<<<tcB_h1, 256, SMEM_TC>>>(B + (size_t)h0 * 128,
                                                w2hi, w2lo,
                                                A + (size_t)h0 * 128, h1);
    cudaStreamWaitEvent(0, evB, 0);

    // ---- layer 2 agg (halves), layer 3 gemm pipelined on side stream ----
    agg128_kernel<<<aggB_h0, 256>>>(rowptr, epack, A, b2, B, 0, h0);
    cudaEventRecord(evC, 0);
    agg128_kernel<<<aggB_h1, 256>>>(rowptr, epack, A, b2, B, h0, h1);

    cudaStreamWaitEvent(s2, evC, 0);
    gemm40_kernel<<<tcB_h0, 320, SMEM40, s2>>>(B, W3, A, h0);
    cudaEventRecord(evD, s2);

    gemm40_kernel<<<tcB_h1, 320, SMEM40>>>(B + (size_t)h0 * 128, W3,
                                           A + (size_t)h0 * DO, h1);
    cudaStreamWaitEvent(0, evD, 0);

    // ---- final: fused agg + bias + log_softmax ----
    agg40_lsm_kernel<<<aggB_full, 256>>>(rowptr, epack, A, b3, out, n);
}

// round 10
// speedup vs baseline: 1.0176x; 1.0176x over previous
#include <cuda_runtime.h>
#include <cuda_bf16.h>
#include <mma.h>
#include <cstdint>

using namespace nvcuda;

// ---------------------------------------------------------------------------
// AdjGCN: 3-layer GCN forward.
//  - CSR-gather aggregation (no float atomics); CSR built on a forked stream;
//    edge payload packed as int2 (src, weight-bits); 2 edges/thread builds.
//  - 128x128 GEMMs on wmma (HMMA), bf16x3 split for near-fp32 accuracy.
// ---------------------------------------------------------------------------

#define MAXN 100000
#define MAXNP 100096   // padded to multiple of 64 (wmma tail-block stores)
#define MAXE 1600000
#define DH   128
#define DO   40
#define LDX  136
#define LDW  136

__device__ float         g_bufA[(size_t)MAXNP * DH];
__device__ float         g_bufB[(size_t)MAXNP * DH];
__device__ int           g_idx64;
__device__ int           g_rowptr[MAXN + 1];
__device__ int           g_deg[MAXN];
__device__ int           g_fill[MAXN];
__device__ int2          g_epack[MAXE];     // (src, weight bits)
__device__ int           g_partials[128];
__device__ __nv_bfloat16 g_w1hi[128 * 128];
__device__ __nv_bfloat16 g_w1lo[128 * 128];
__device__ __nv_bfloat16 g_w2hi[128 * 128];
__device__ __nv_bfloat16 g_w2lo[128 * 128];

// ------------------------------ CSR build ---------------------------------
__global__ void deg_zero_kernel(int* __restrict__ deg, int n,
                                const void* ei, int n_nodes) {
    int i = blockIdx.x * blockDim.x + threadIdx.x;
    if (i < n) deg[i] = 0;
    if (blockIdx.x == 0 && threadIdx.x == 0) {
        const long long* p = (const long long*)ei;
        int ok64 = 1;
        for (int k = 0; k < 32; k++) {
            long long v = p[k];
            if (v < 0 || v >= n_nodes) { ok64 = 0; break; }
        }
        g_idx64 = ok64;
    }
}

// 2 edges per thread; dst-array base is 16B/8B aligned (ne even).
__global__ void deg_count_kernel(const void* __restrict__ ei, int ne,
                                 int* __restrict__ deg) {
    int e = (blockIdx.x * blockDim.x + threadIdx.x) * 2;
    if (e >= ne) return;
    int d0, d1 = -1;
    if (g_idx64) {
        const long long* p = (const long long*)ei + ne;
        if (e + 1 < ne) {
            longlong2 v = *(const longlong2*)(p + e);
            d0 = (int)v.x; d1 = (int)v.y;
        } else d0 = (int)p[e];
    } else {
        const int* p = (const int*)ei + ne;
        if (e + 1 < ne) {
            int2 v = *(const int2*)(p + e);
            d0 = v.x; d1 = v.y;
        } else d0 = p[e];
    }
    atomicAdd(&deg[d0], 1);
    if (d1 >= 0) atomicAdd(&deg[d1], 1);
}

__global__ void scan_block_kernel(const int* __restrict__ deg,
                                  int* __restrict__ rowptr,
                                  int* __restrict__ partials, int n) {
    __shared__ int sm[1024];
    const int tid = threadIdx.x;
    int i = blockIdx.x * 1024 + tid;
    int v = (i < n) ? deg[i] : 0;
    sm[tid] = v;
    __syncthreads();
#pragma unroll
    for (int o = 1; o < 1024; o <<= 1) {
        int t = (tid >= o) ? sm[tid - o] : 0;
        __syncthreads();
        sm[tid] += t;
        __syncthreads();
    }
    if (i < n) rowptr[i] = sm[tid] - v;
    if (tid == 1023) partials[blockIdx.x] = sm[1023];
}

__global__ void scan_partials_kernel(int* __restrict__ partials, int nb) {
    __shared__ int sm[128];
    const int tid = threadIdx.x;
    int v = (tid < nb) ? partials[tid] : 0;
    sm[tid] = v;
    __syncthreads();
#pragma unroll
    for (int o = 1; o < 128; o <<= 1) {
        int t = (tid >= o) ? sm[tid - o] : 0;
        __syncthreads();
        sm[tid] += t;
        __syncthreads();
    }
    if (tid < nb) partials[tid] = sm[tid] - v;
}

__global__ void scan_add_kernel(int* __restrict__ rowptr,
                                const int* __restrict__ partials,
                                int* __restrict__ fill, int n, int ne) {
    int i = blockIdx.x * blockDim.x + threadIdx.x;
    if (i < n) {
        int v = rowptr[i] + partials[i >> 10];
        rowptr[i] = v;
        fill[i] = v;
    }
    if (i == 0) rowptr[n] = ne;
}

// 2 edges per thread.
__global__ void csr_fill_kernel(const void* __restrict__ ei,
                                const float* __restrict__ ew, int ne,
                                int* __restrict__ fill,
                                int2* __restrict__ epack) {
    int e = (blockIdx.x * blockDim.x + threadIdx.x) * 2;
    if (e >= ne) return;
    int s0, d0, s1 = -1, d1 = -1;
    float w0, w1 = 0.f;
    if (g_idx64) {
        const long long* ps = (const long long*)ei;
        const long long* pd = ps + ne;
        if (e + 1 < ne) {
            longlong2 sv = *(const longlong2*)(ps + e);
            longlong2 dv = *(const longlong2*)(pd + e);
            float2 wv = *(const float2*)(ew + e);
            s0 = (int)sv.x; s1 = (int)sv.y;
            d0 = (int)dv.x; d1 = (int)dv.y;
            w0 = wv.x; w1 = wv.y;
        } else { s0 = (int)ps[e]; d0 = (int)pd[e]; w0 = ew[e]; }
    } else {
        const int* ps = (const int*)ei;
        const int* pd = ps + ne;
        if (e + 1 < ne) {
            int2 sv = *(const int2*)(ps + e);
            int2 dv = *(const int2*)(pd + e);
            float2 wv = *(const float2*)(ew + e);
            s0 = sv.x; s1 = sv.y; d0 = dv.x; d1 = dv.y;
            w0 = wv.x; w1 = wv.y;
        } else { s0 = ps[e]; d0 = pd[e]; w0 = ew[e]; }
    }
    int p0 = atomicAdd(&fill[d0], 1);
    epack[p0] = make_int2(s0, __float_as_int(w0));
    if (s1 >= 0) {
        int p1 = atomicAdd(&fill[d1], 1);
        epack[p1] = make_int2(s1, __float_as_int(w1));
    }
}

// ------------- W prep: fp32 -> bf16 hi/lo for W1 and W2, fused -------------
__global__ void prep_w2_kernel(const float* __restrict__ Wa,
                               __nv_bfloat16* __restrict__ ahi,
                               __nv_bfloat16* __restrict__ alo,
                               const float* __restrict__ Wb,
                               __nv_bfloat16* __restrict__ bhi,
                               __nv_bfloat16* __restrict__ blo) {
    int i = blockIdx.x * blockDim.x + threadIdx.x;
    if (i < 128 * 128) {
        float w = Wa[i];
        __nv_bfloat16 h = __float2bfloat16_rn(w);
        ahi[i] = h;
        alo[i] = __float2bfloat16_rn(w - __bfloat162float(h));
    } else if (i < 2 * 128 * 128) {
        int k = i - 128 * 128;
        float w = Wb[k];
        __nv_bfloat16 h = __float2bfloat16_rn(w);
        bhi[k] = h;
        blo[k] = __float2bfloat16_rn(w - __bfloat162float(h));
    }
}

// -------------------- tensor-path GEMM (wmma bf16x3) -----------------------
__global__ void gemm128_tc_kernel(const float* __restrict__ X,
                                  const __nv_bfloat16* __restrict__ Whi,
                                  const __nv_bfloat16* __restrict__ Wlo,
                                  float* __restrict__ Y, int nrows) {
    extern __shared__ char smem[];
    __nv_bfloat16* xhi = (__nv_bfloat16*)smem;
    __nv_bfloat16* xlo = xhi + 64 * LDX;
    __nv_bfloat16* wh  = xlo + 64 * LDX;
    __nv_bfloat16* wl  = wh + 128 * LDW;
    const int tid = threadIdx.x;
    const int row0 = blockIdx.x * 64;

    {
        const float4* X4 = (const float4*)X;
#pragma unroll
        for (int i = tid; i < 64 * 32; i += 256) {
            int r = i >> 5, kq = i & 31;
            float4 v = (row0 + r < nrows)
                           ? X4[(size_t)(row0 + r) * 32 + kq]
                           : make_float4(0.f, 0.f, 0.f, 0.f);
            __nv_bfloat16 hx = __float2bfloat16_rn(v.x);
            __nv_bfloat16 hy = __float2bfloat16_rn(v.y);
            __nv_bfloat16 hz = __float2bfloat16_rn(v.z);
            __nv_bfloat16 hw = __float2bfloat16_rn(v.w);
            __nv_bfloat162 hp0 = __halves2bfloat162(hx, hy);
            __nv_bfloat162 hp1 = __halves2bfloat162(hz, hw);
            uint64_t hword = (uint64_t)(*(uint32_t*)&hp0)
                           | ((uint64_t)(*(uint32_t*)&hp1) << 32);
            *(uint64_t*)&xhi[r * LDX + kq * 4] = hword;
            __nv_bfloat162 lp0 = __halves2bfloat162(
                __float2bfloat16_rn(v.x - __bfloat162float(hx)),
                __float2bfloat16_rn(v.y - __bfloat162float(hy)));
            __nv_bfloat162 lp1 = __halves2bfloat162(
                __float2bfloat16_rn(v.z - __bfloat162float(hz)),
                __float2bfloat16_rn(v.w - __bfloat162float(hw)));
            uint64_t lword = (uint64_t)(*(uint32_t*)&lp0)
                           | ((uint64_t)(*(uint32_t*)&lp1) << 32);
            *(uint64_t*)&xlo[r * LDX + kq * 4] = lword;
        }
    }
    {
        const int4* h4 = (const int4*)Whi;
        const int4* l4 = (const int4*)Wlo;
#pragma unroll
        for (int i = tid; i < 2048; i += 256) {
            int k = i >> 4, seg = i & 15;
            *(int4*)&wh[k * LDW + seg * 8] = h4[i];
            *(int4*)&wl[k * LDW + seg * 8] = l4[i];
        }
    }
    __syncthreads();

    const int w  = tid >> 5;
    const int wr = w >> 2;
    const int wc = w & 3;

    wmma::fragment<wmma::accumulator, 16, 16, 16, float> acc[2][2];
#pragma unroll
    for (int i = 0; i < 2; i++)
#pragma unroll
        for (int j = 0; j < 2; j++) wmma::fill_fragment(acc[i][j], 0.f);

#pragma unroll
    for (int ks = 0; ks < 8; ks++) {
        const int k0 = ks * 16;
        wmma::fragment<wmma::matrix_a, 16, 16, 16, __nv_bfloat16,
                       wmma::row_major> ah[2], al[2];
        wmma::fragment<wmma::matrix_b, 16, 16, 16, __nv_bfloat16,
                       wmma::row_major> bh[2], bl[2];
#pragma unroll
        for (int i = 0; i < 2; i++) {
            wmma::load_matrix_sync(ah[i], &xhi[(wr * 32 + i * 16) * LDX + k0], LDX);
            wmma::load_matrix_sync(al[i], &xlo[(wr * 32 + i * 16) * LDX + k0], LDX);
        }
#pragma unroll
        for (int j = 0; j < 2; j++) {
            wmma::load_matrix_sync(bh[j], &wh[k0 * LDW + wc * 32 + j * 16], LDW);
            wmma::load_matrix_sync(bl[j], &wl[k0 * LDW + wc * 32 + j * 16], LDW);
        }
#pragma unroll
        for (int i = 0; i < 2; i++)
#pragma unroll
            for (int j = 0; j < 2; j++) {
                wmma::mma_sync(acc[i][j], ah[i], bh[j], acc[i][j]);
                wmma::mma_sync(acc[i][j], ah[i], bl[j], acc[i][j]);
                wmma::mma_sync(acc[i][j], al[i], bh[j], acc[i][j]);
            }
    }

#pragma unroll
    for (int i = 0; i < 2; i++)
#pragma unroll
        for (int j = 0; j < 2; j++) {
            int gr = row0 + wr * 32 + i * 16;
            int gc = wc * 32 + j * 16;
            wmma::store_matrix_sync(&Y[(size_t)gr * 128 + gc], acc[i][j],
                                    128, wmma::mem_row_major);
        }
}

// ------------------------- SIMT GEMM, D_OUT=40 ------------------------------
__global__ void gemm40_kernel(const float* __restrict__ X,
                              const float* __restrict__ W,
                              float* __restrict__ Y, int nrows) {
    extern __shared__ float sm[];
    float* Ws = sm;
    float* Xs = sm + 128 * DO;
    const int tid = threadIdx.x;

    for (int i = tid; i < 128 * DO; i += 320) Ws[i] = W[i];

    const int row0 = blockIdx.x * 64;
    const float4* X4 = (const float4*)X;
    float4* Xs4 = (float4*)Xs;
    for (int i = tid; i < 64 * 32; i += 320) {
        int gr = row0 + (i >> 5);
        Xs4[i] = (gr < nrows) ? X4[(size_t)gr * 32 + (i & 31)]
                              : make_float4(0.f, 0.f, 0.f, 0.f);
    }
    __syncthreads();

    const int c  = tid % DO;
    const int rg = tid / DO;
    float acc[8];
#pragma unroll
    for (int r = 0; r < 8; r++) acc[r] = 0.f;
    const float4* xb4 = (const float4*)(Xs + rg * 8 * 128);

#pragma unroll 4
    for (int k4 = 0; k4 < 32; k4++) {
        float w0 = Ws[(4 * k4 + 0) * DO + c];
        float w1 = Ws[(4 * k4 + 1) * DO + c];
        float w2 = Ws[(4 * k4 + 2) * DO + c];
        float w3 = Ws[(4 * k4 + 3) * DO + c];
#pragma unroll
        for (int r = 0; r < 8; r++) {
            float4 xv = xb4[r * 32 + k4];
            acc[r] += xv.x * w0 + xv.y * w1 + xv.z * w2 + xv.w * w3;
        }
    }
#pragma unroll
    for (int r = 0; r < 8; r++) {
        int gr = row0 + rg * 8 + r;
        if (gr < nrows) Y[(size_t)gr * DO + c] = acc[r];
    }
}

// ----------------------- CSR gather aggregation ----------------------------
__global__ void agg128_kernel(const int* __restrict__ rowptr,
                              const int2* __restrict__ epack,
                              const float* __restrict__ H,
                              const float* __restrict__ bias,
                              float* __restrict__ Y, int n) {
    int node = blockIdx.x * 8 + (threadIdx.x >> 5);
    if (node >= n) return;
    const int lane = threadIdx.x & 31;
    int beg = rowptr[node];
    int end = rowptr[node + 1];

    float4 acc = make_float4(0.f, 0.f, 0.f, 0.f);
    int j = beg;
    for (; j + 3 < end; j += 4) {
        int2 e0 = epack[j];     int2 e1 = epack[j + 1];
        int2 e2 = epack[j + 2]; int2 e3 = epack[j + 3];
        float w0 = __int_as_float(e0.y), w1 = __int_as_float(e1.y);
        float w2 = __int_as_float(e2.y), w3 = __int_as_float(e3.y);
        float4 v0 = ((const float4*)(H + (size_t)e0.x * 128))[lane];
        float4 v1 = ((const float4*)(H + (size_t)e1.x * 128))[lane];
        float4 v2 = ((const float4*)(H + (size_t)e2.x * 128))[lane];
        float4 v3 = ((const float4*)(H + (size_t)e3.x * 128))[lane];
        acc.x += v0.x * w0 + v1.x * w1 + v2.x * w2 + v3.x * w3;
        acc.y += v0.y * w0 + v1.y * w1 + v2.y * w2 + v3.y * w3;
        acc.z += v0.z * w0 + v1.z * w1 + v2.z * w2 + v3.z * w3;
        acc.w += v0.w * w0 + v1.w * w1 + v2.w * w2 + v3.w * w3;
    }
    for (; j < end; j++) {
        int2 e = epack[j];
        float w = __int_as_float(e.y);
        float4 v = ((const float4*)(H + (size_t)e.x * 128))[lane];
        acc.x += v.x * w; acc.y += v.y * w; acc.z += v.z * w; acc.w += v.w * w;
    }

    float4 b = ((const float4*)bias)[lane];
    acc.x = fmaxf(acc.x + b.x, 0.f);
    acc.y = fmaxf(acc.y + b.y, 0.f);
    acc.z = fmaxf(acc.z + b.z, 0.f);
    acc.w = fmaxf(acc.w + b.w, 0.f);
    ((float4*)(Y + (size_t)node * 128))[lane] = acc;
}

__global__ void agg40_lsm_kernel(const int* __restrict__ rowptr,
                                 const int2* __restrict__ epack,
                                 const float* __restrict__ H,
                                 const float* __restrict__ b,
                                 float* __restrict__ out, int n) {
    int node = blockIdx.x * 8 + (threadIdx.x >> 5);
    if (node >= n) return;
    const int lane = threadIdx.x & 31;
    int beg = rowptr[node];
    int end = rowptr[node + 1];

    float a0 = 0.f, a1 = 0.f;
    int j = beg;
    for (; j + 1 < end; j += 2) {
        int2 e0 = epack[j]; int2 e1 = epack[j + 1];
        float w0 = __int_as_float(e0.y), w1 = __int_as_float(e1.y);
        const float* h0 = H + (size_t)e0.x * DO;
        const float* h1 = H + (size_t)e1.x * DO;
        a0 += h0[lane] * w0 + h1[lane] * w1;
        if (lane < 8) a1 += h0[32 + lane] * w0 + h1[32 + lane] * w1;
    }
    if (j < end) {
        int2 e = epack[j];
        float w = __int_as_float(e.y);
        const float* hs = H + (size_t)e.x * DO;
        a0 += hs[lane] * w;
        if (lane < 8) a1 += hs[32 + lane] * w;
    }

    float v0 = a0 + b[lane];
    float v1 = (lane < 8) ? (a1 + b[32 + lane]) : -1e30f;

    float m = fmaxf(v0, v1);
#pragma unroll
    for (int o = 16; o; o >>= 1) m = fmaxf(m, __shfl_xor_sync(0xffffffffu, m, o));

    float sum = __expf(v0 - m) + ((lane < 8) ? __expf(v1 - m) : 0.f);
#pragma unroll
    for (int o = 16; o; o >>= 1) sum += __shfl_xor_sync(0xffffffffu, sum, o);

    float lse = m + __logf(sum);
    out[(size_t)node * DO + lane] = v0 - lse;
    if (lane < 8) out[(size_t)node * DO + 32 + lane] = v1 - lse;
}

// ---------------------------------------------------------------------------
extern "C" void kernel_launch(void* const* d_in, const int* in_sizes, int n_in,
                              void* d_out, int out_size) {
    const float* x  = (const float*)d_in[0];
    const void*  ei = d_in[1];
    const float* ew = (const float*)d_in[2];
    const float* W1 = (const float*)d_in[3];
    const float* b1 = (const float*)d_in[4];
    const float* W2 = (const float*)d_in[5];
    const float* b2 = (const float*)d_in[6];
    const float* W3 = (const float*)d_in[7];
    const float* b3 = (const float*)d_in[8];
    float* out = (float*)d_out;

    const int n  = in_sizes[0] / DH;
    int ne = in_sizes[1] / 2;
    if (ne > MAXE) ne = MAXE;
    (void)n_in; (void)out_size;

    float *A, *B;
    int *rowptr, *deg, *fill, *partials;
    int2* epack;
    __nv_bfloat16 *w1hi, *w1lo, *w2hi, *w2lo;
    cudaGetSymbolAddress((void**)&A, g_bufA);
    cudaGetSymbolAddress((void**)&B, g_bufB);
    cudaGetSymbolAddress((void**)&rowptr, g_rowptr);
    cudaGetSymbolAddress((void**)&deg, g_deg);
    cudaGetSymbolAddress((void**)&fill, g_fill);
    cudaGetSymbolAddress((void**)&epack, g_epack);
    cudaGetSymbolAddress((void**)&partials, g_partials);
    cudaGetSymbolAddress((void**)&w1hi, g_w1hi);
    cudaGetSymbolAddress((void**)&w1lo, g_w1lo);
    cudaGetSymbolAddress((void**)&w2hi, g_w2hi);
    cudaGetSymbolAddress((void**)&w2lo, g_w2lo);

    const int SMEM_TC = (2 * 64 * LDX + 2 * 128 * LDW) * (int)sizeof(__nv_bfloat16);
    const int SMEM40  = (128 * DO + 64 * 128) * (int)sizeof(float);
    cudaFuncSetAttribute(gemm128_tc_kernel,
                         cudaFuncAttributeMaxDynamicSharedMemorySize, SMEM_TC);
    cudaFuncSetAttribute(gemm40_kernel,
                         cudaFuncAttributeMaxDynamicSharedMemorySize, SMEM40);

    const int tcBlocks       = (n + 63) / 64;
    const int nodeWarpBlocks = (n + 7) / 8;
    const int scanBlocks     = (n + 1023) / 1024;
    const int edge2Blocks    = ((ne + 1) / 2 + 255) / 256;

    static cudaStream_t s2 = nullptr;
    static cudaEvent_t evFork = nullptr, evJoin = nullptr;
    if (s2 == nullptr) {
        cudaStreamCreateWithFlags(&s2, cudaStreamNonBlocking);
        cudaEventCreateWithFlags(&evFork, cudaEventDisableTiming);
        cudaEventCreateWithFlags(&evJoin, cudaEventDisableTiming);
    }

    // ---- fork: CSR build on side stream ----
    cudaEventRecord(evFork, 0);
    cudaStreamWaitEvent(s2, evFork, 0);
    deg_zero_kernel<<<(n + 255) / 256, 256, 0, s2>>>(deg, n, ei, n);
    deg_count_kernel<<<edge2Blocks, 256, 0, s2>>>(ei, ne, deg);
    scan_block_kernel<<<scanBlocks, 1024, 0, s2>>>(deg, rowptr, partials, n);
    scan_partials_kernel<<<1, 128, 0, s2>>>(partials, scanBlocks);
    scan_add_kernel<<<(n + 255) / 256, 256, 0, s2>>>(rowptr, partials, fill, n, ne);
    csr_fill_kernel<<<edge2Blocks, 256, 0, s2>>>(ei, ew, ne, fill, epack);
    cudaEventRecord(evJoin, s2);

    // ---- main stream: W prep + layer-1 GEMM overlap the CSR build ----
    prep_w2_kernel<<<128, 256>>>(W1, w1hi, w1lo, W2, w2hi, w2lo);
    gemm128_tc_kernel<<<tcBlocks, 256, SMEM_TC>>>(x, w1hi, w1lo, A, n);

    // ---- join ----
    cudaStreamWaitEvent(0, evJoin, 0);

    // ---- layer 1 ----
    agg128_kernel<<<nodeWarpBlocks, 256>>>(rowptr, epack, A, b1, B, n);
    // ---- layer 2 ----
    gemm128_tc_kernel<<<tcBlocks, 256, SMEM_TC>>>(B, w2hi, w2lo, A, n);
    agg128_kernel<<<nodeWarpBlocks, 256>>>(rowptr, epack, A, b2, B, n);
    // ---- layer 3 (D_OUT = 40) ----
    gemm40_kernel<<<tcBlocks, 320, SMEM40>>>(B, W3, A, n);
    agg40_lsm_kernel<<<nodeWarpBlocks, 256>>>(rowptr, epack, A, b3, out, n);
}

// round 11
// speedup vs baseline: 1.0959x; 1.0770x over previous
#include <cuda_runtime.h>
#include <cuda_bf16.h>
#include <cuda_fp16.h>
#include <mma.h>
#include <cstdint>

using namespace nvcuda;

// ---------------------------------------------------------------------------
// AdjGCN: 3-layer GCN forward.
//  - CSR-gather aggregation (no float atomics); CSR built on a forked stream;
//    edge payload packed as int2 (src, weight-bits).
//  - 128x128 GEMMs on wmma (HMMA), bf16x3 split, fp32 accumulate.
//  - H (the gathered operand) stored fp16: halves aggregation L2 traffic.
//    Aggregation accumulates fp32; agg outputs stay fp32.
// ---------------------------------------------------------------------------

#define MAXN 100000
#define MAXNP 100096
#define MAXE 1600000
#define DH   128
#define DO   40
#define LDX  136
#define LDW  136
#define LDS  132      // float staging leading dim (mult of 4)

__device__ float         g_bufA[(size_t)MAXNP * DH];   // holds fp16 H (reused)
__device__ float         g_bufB[(size_t)MAXNP * DH];   // fp32 agg outputs
__device__ int           g_idx64;
__device__ int           g_rowptr[MAXN + 1];
__device__ int           g_deg[MAXN];
__device__ int           g_fill[MAXN];
__device__ int2          g_epack[MAXE];
__device__ int           g_partials[128];
__device__ __nv_bfloat16 g_w1hi[128 * 128];
__device__ __nv_bfloat16 g_w1lo[128 * 128];
__device__ __nv_bfloat16 g_w2hi[128 * 128];
__device__ __nv_bfloat16 g_w2lo[128 * 128];

// ------------------------------ CSR build ---------------------------------
__global__ void deg_zero_kernel(int* __restrict__ deg, int n,
                                const void* ei, int n_nodes) {
    int i = blockIdx.x * blockDim.x + threadIdx.x;
    if (i < n) deg[i] = 0;
    if (blockIdx.x == 0 && threadIdx.x == 0) {
        const long long* p = (const long long*)ei;
        int ok64 = 1;
        for (int k = 0; k < 32; k++) {
            long long v = p[k];
            if (v < 0 || v >= n_nodes) { ok64 = 0; break; }
        }
        g_idx64 = ok64;
    }
}

__global__ void deg_count_kernel(const void* __restrict__ ei, int ne,
                                 int* __restrict__ deg) {
    int e = (blockIdx.x * blockDim.x + threadIdx.x) * 2;
    if (e >= ne) return;
    int d0, d1 = -1;
    if (g_idx64) {
        const long long* p = (const long long*)ei + ne;
        if (e + 1 < ne) {
            longlong2 v = *(const longlong2*)(p + e);
            d0 = (int)v.x; d1 = (int)v.y;
        } else d0 = (int)p[e];
    } else {
        const int* p = (const int*)ei + ne;
        if (e + 1 < ne) {
            int2 v = *(const int2*)(p + e);
            d0 = v.x; d1 = v.y;
        } else d0 = p[e];
    }
    atomicAdd(&deg[d0], 1);
    if (d1 >= 0) atomicAdd(&deg[d1], 1);
}

__global__ void scan_block_kernel(const int* __restrict__ deg,
                                  int* __restrict__ rowptr,
                                  int* __restrict__ partials, int n) {
    __shared__ int sm[1024];
    const int tid = threadIdx.x;
    int i = blockIdx.x * 1024 + tid;
    int v = (i < n) ? deg[i] : 0;
    sm[tid] = v;
    __syncthreads();
#pragma unroll
    for (int o = 1; o < 1024; o <<= 1) {
        int t = (tid >= o) ? sm[tid - o] : 0;
        __syncthreads();
        sm[tid] += t;
        __syncthreads();
    }
    if (i < n) rowptr[i] = sm[tid] - v;
    if (tid == 1023) partials[blockIdx.x] = sm[1023];
}

__global__ void scan_partials_kernel(int* __restrict__ partials, int nb) {
    __shared__ int sm[128];
    const int tid = threadIdx.x;
    int v = (tid < nb) ? partials[tid] : 0;
    sm[tid] = v;
    __syncthreads();
#pragma unroll
    for (int o = 1; o < 128; o <<= 1) {
        int t = (tid >= o) ? sm[tid - o] : 0;
        __syncthreads();
        sm[tid] += t;
        __syncthreads();
    }
    if (tid < nb) partials[tid] = sm[tid] - v;
}

__global__ void scan_add_kernel(int* __restrict__ rowptr,
                                const int* __restrict__ partials,
                                int* __restrict__ fill, int n, int ne) {
    int i = blockIdx.x * blockDim.x + threadIdx.x;
    if (i < n) {
        int v = rowptr[i] + partials[i >> 10];
        rowptr[i] = v;
        fill[i] = v;
    }
    if (i == 0) rowptr[n] = ne;
}

__global__ void csr_fill_kernel(const void* __restrict__ ei,
                                const float* __restrict__ ew, int ne,
                                int* __restrict__ fill,
                                int2* __restrict__ epack) {
    int e = (blockIdx.x * blockDim.x + threadIdx.x) * 2;
    if (e >= ne) return;
    int s0, d0, s1 = -1, d1 = -1;
    float w0, w1 = 0.f;
    if (g_idx64) {
        const long long* ps = (const long long*)ei;
        const long long* pd = ps + ne;
        if (e + 1 < ne) {
            longlong2 sv = *(const longlong2*)(ps + e);
            longlong2 dv = *(const longlong2*)(pd + e);
            float2 wv = *(const float2*)(ew + e);
            s0 = (int)sv.x; s1 = (int)sv.y;
            d0 = (int)dv.x; d1 = (int)dv.y;
            w0 = wv.x; w1 = wv.y;
        } else { s0 = (int)ps[e]; d0 = (int)pd[e]; w0 = ew[e]; }
    } else {
        const int* ps = (const int*)ei;
        const int* pd = ps + ne;
        if (e + 1 < ne) {
            int2 sv = *(const int2*)(ps + e);
            int2 dv = *(const int2*)(pd + e);
            float2 wv = *(const float2*)(ew + e);
            s0 = sv.x; s1 = sv.y; d0 = dv.x; d1 = dv.y;
            w0 = wv.x; w1 = wv.y;
        } else { s0 = ps[e]; d0 = pd[e]; w0 = ew[e]; }
    }
    int p0 = atomicAdd(&fill[d0], 1);
    epack[p0] = make_int2(s0, __float_as_int(w0));
    if (s1 >= 0) {
        int p1 = atomicAdd(&fill[d1], 1);
        epack[p1] = make_int2(s1, __float_as_int(w1));
    }
}

// ------------- W prep: fp32 -> bf16 hi/lo for W1 and W2, fused -------------
__global__ void prep_w2_kernel(const float* __restrict__ Wa,
                               __nv_bfloat16* __restrict__ ahi,
                               __nv_bfloat16* __restrict__ alo,
                               const float* __restrict__ Wb,
                               __nv_bfloat16* __restrict__ bhi,
                               __nv_bfloat16* __restrict__ blo) {
    int i = blockIdx.x * blockDim.x + threadIdx.x;
    if (i < 128 * 128) {
        float w = Wa[i];
        __nv_bfloat16 h = __float2bfloat16_rn(w);
        ahi[i] = h;
        alo[i] = __float2bfloat16_rn(w - __bfloat162float(h));
    } else if (i < 2 * 128 * 128) {
        int k = i - 128 * 128;
        float w = Wb[k];
        __nv_bfloat16 h = __float2bfloat16_rn(w);
        bhi[k] = h;
        blo[k] = __float2bfloat16_rn(w - __bfloat162float(h));
    }
}

// -------------------- tensor-path GEMM (wmma bf16x3) -----------------------
// Output H in fp16 (row-major N x 128 halves). Staging via smem.
__global__ void gemm128_tc_kernel(const float* __restrict__ X,
                                  const __nv_bfloat16* __restrict__ Whi,
                                  const __nv_bfloat16* __restrict__ Wlo,
                                  __half* __restrict__ Yh, int nrows) {
    extern __shared__ char smem[];
    __nv_bfloat16* xhi = (__nv_bfloat16*)smem;
    __nv_bfloat16* xlo = xhi + 64 * LDX;
    __nv_bfloat16* wh  = xlo + 64 * LDX;
    __nv_bfloat16* wl  = wh + 128 * LDW;
    const int tid = threadIdx.x;
    const int row0 = blockIdx.x * 64;

    {
        const float4* X4 = (const float4*)X;
#pragma unroll
        for (int i = tid; i < 64 * 32; i += 256) {
            int r = i >> 5, kq = i & 31;
            float4 v = (row0 + r < nrows)
                           ? X4[(size_t)(row0 + r) * 32 + kq]
                           : make_float4(0.f, 0.f, 0.f, 0.f);
            __nv_bfloat16 hx = __float2bfloat16_rn(v.x);
            __nv_bfloat16 hy = __float2bfloat16_rn(v.y);
            __nv_bfloat16 hz = __float2bfloat16_rn(v.z);
            __nv_bfloat16 hw = __float2bfloat16_rn(v.w);
            __nv_bfloat162 hp0 = __halves2bfloat162(hx, hy);
            __nv_bfloat162 hp1 = __halves2bfloat162(hz, hw);
            uint64_t hword = (uint64_t)(*(uint32_t*)&hp0)
                           | ((uint64_t)(*(uint32_t*)&hp1) << 32);
            *(uint64_t*)&xhi[r * LDX + kq * 4] = hword;
            __nv_bfloat162 lp0 = __halves2bfloat162(
                __float2bfloat16_rn(v.x - __bfloat162float(hx)),
                __float2bfloat16_rn(v.y - __bfloat162float(hy)));
            __nv_bfloat162 lp1 = __halves2bfloat162(
                __float2bfloat16_rn(v.z - __bfloat162float(hz)),
                __float2bfloat16_rn(v.w - __bfloat162float(hw)));
            uint64_t lword = (uint64_t)(*(uint32_t*)&lp0)
                           | ((uint64_t)(*(uint32_t*)&lp1) << 32);
            *(uint64_t*)&xlo[r * LDX + kq * 4] = lword;
        }
    }
    {
        const int4* h4 = (const int4*)Whi;
        const int4* l4 = (const int4*)Wlo;
#pragma unroll
        for (int i = tid; i < 2048; i += 256) {
            int k = i >> 4, seg = i & 15;
            *(int4*)&wh[k * LDW + seg * 8] = h4[i];
            *(int4*)&wl[k * LDW + seg * 8] = l4[i];
        }
    }
    __syncthreads();

    const int w  = tid >> 5;
    const int wr = w >> 2;
    const int wc = w & 3;

    wmma::fragment<wmma::accumulator, 16, 16, 16, float> acc[2][2];
#pragma unroll
    for (int i = 0; i < 2; i++)
#pragma unroll
        for (int j = 0; j < 2; j++) wmma::fill_fragment(acc[i][j], 0.f);

#pragma unroll
    for (int ks = 0; ks < 8; ks++) {
        const int k0 = ks * 16;
        wmma::fragment<wmma::matrix_a, 16, 16, 16, __nv_bfloat16,
                       wmma::row_major> ah[2], al[2];
        wmma::fragment<wmma::matrix_b, 16, 16, 16, __nv_bfloat16,
                       wmma::row_major> bh[2], bl[2];
#pragma unroll
        for (int i = 0; i < 2; i++) {
            wmma::load_matrix_sync(ah[i], &xhi[(wr * 32 + i * 16) * LDX + k0], LDX);
            wmma::load_matrix_sync(al[i], &xlo[(wr * 32 + i * 16) * LDX + k0], LDX);
        }
#pragma unroll
        for (int j = 0; j < 2; j++) {
            wmma::load_matrix_sync(bh[j], &wh[k0 * LDW + wc * 32 + j * 16], LDW);
            wmma::load_matrix_sync(bl[j], &wl[k0 * LDW + wc * 32 + j * 16], LDW);
        }
#pragma unroll
        for (int i = 0; i < 2; i++)
#pragma unroll
            for (int j = 0; j < 2; j++) {
                wmma::mma_sync(acc[i][j], ah[i], bh[j], acc[i][j]);
                wmma::mma_sync(acc[i][j], ah[i], bl[j], acc[i][j]);
                wmma::mma_sync(acc[i][j], al[i], bh[j], acc[i][j]);
            }
    }

    // Stage accumulators in smem (reuse xhi/xlo region), convert to fp16.
    __syncthreads();
    float* stage = (float*)smem;   // 64 x LDS floats = 33792 B (fits region)
#pragma unroll
    for (int i = 0; i < 2; i++)
#pragma unroll
        for (int j = 0; j < 2; j++) {
            wmma::store_matrix_sync(&stage[(wr * 32 + i * 16) * LDS
                                           + wc * 32 + j * 16],
                                    acc[i][j], LDS, wmma::mem_row_major);
        }
    __syncthreads();
    // 64 rows x 64 half2 columns; Y padded to MAXNP rows, no guard needed.
    __half2* Y2 = (__half2*)Yh;
#pragma unroll
    for (int i = tid; i < 64 * 64; i += 256) {
        int r = i >> 6, c2 = i & 63;
        float a = stage[r * LDS + 2 * c2];
        float b = stage[r * LDS + 2 * c2 + 1];
        Y2[(size_t)(row0 + r) * 64 + c2] = __floats2half2_rn(a, b);
    }
}

// ------------------------- SIMT GEMM, D_OUT=40 (fp16 out) ------------------
__global__ void gemm40_kernel(const float* __restrict__ X,
                              const float* __restrict__ W,
                              __half* __restrict__ Yh, int nrows) {
    extern __shared__ float sm[];
    float* Ws = sm;
    float* Xs = sm + 128 * DO;
    const int tid = threadIdx.x;

    for (int i = tid; i < 128 * DO; i += 320) Ws[i] = W[i];

    const int row0 = blockIdx.x * 64;
    const float4* X4 = (const float4*)X;
    float4* Xs4 = (float4*)Xs;
    for (int i = tid; i < 64 * 32; i += 320) {
        int gr = row0 + (i >> 5);
        Xs4[i] = (gr < nrows) ? X4[(size_t)gr * 32 + (i & 31)]
                              : make_float4(0.f, 0.f, 0.f, 0.f);
    }
    __syncthreads();

    const int c  = tid % DO;
    const int rg = tid / DO;
    float acc[8];
#pragma unroll
    for (int r = 0; r < 8; r++) acc[r] = 0.f;
    const float4* xb4 = (const float4*)(Xs + rg * 8 * 128);

#pragma unroll 4
    for (int k4 = 0; k4 < 32; k4++) {
        float w0 = Ws[(4 * k4 + 0) * DO + c];
        float w1 = Ws[(4 * k4 + 1) * DO + c];
        float w2 = Ws[(4 * k4 + 2) * DO + c];
        float w3 = Ws[(4 * k4 + 3) * DO + c];
#pragma unroll
        for (int r = 0; r < 8; r++) {
            float4 xv = xb4[r * 32 + k4];
            acc[r] += xv.x * w0 + xv.y * w1 + xv.z * w2 + xv.w * w3;
        }
    }
#pragma unroll
    for (int r = 0; r < 8; r++) {
        int gr = row0 + rg * 8 + r;
        if (gr < nrows) Yh[(size_t)gr * DO + c] = __float2half_rn(acc[r]);
    }
}

// ----------------------- CSR gather aggregation ----------------------------
// H in fp16 (256 B/row). Lane owns cols 4l..4l+3 = one uint2 (2 half2).
__global__ void agg128_kernel(const int* __restrict__ rowptr,
                              const int2* __restrict__ epack,
                              const __half* __restrict__ H,
                              const float* __restrict__ bias,
                              float* __restrict__ Y, int n) {
    int node = blockIdx.x * 8 + (threadIdx.x >> 5);
    if (node >= n) return;
    const int lane = threadIdx.x & 31;
    int beg = rowptr[node];
    int end = rowptr[node + 1];

    float4 acc = make_float4(0.f, 0.f, 0.f, 0.f);
    int j = beg;
    for (; j + 3 < end; j += 4) {
        int2 e0 = epack[j];     int2 e1 = epack[j + 1];
        int2 e2 = epack[j + 2]; int2 e3 = epack[j + 3];
        float w0 = __int_as_float(e0.y), w1 = __int_as_float(e1.y);
        float w2 = __int_as_float(e2.y), w3 = __int_as_float(e3.y);
        uint2 u0 = ((const uint2*)(H + (size_t)e0.x * 128))[lane];
        uint2 u1 = ((const uint2*)(H + (size_t)e1.x * 128))[lane];
        uint2 u2 = ((const uint2*)(H + (size_t)e2.x * 128))[lane];
        uint2 u3 = ((const uint2*)(H + (size_t)e3.x * 128))[lane];
        float2 a0 = __half22float2(*(__half2*)&u0.x);
        float2 b0 = __half22float2(*(__half2*)&u0.y);
        float2 a1 = __half22float2(*(__half2*)&u1.x);
        float2 b1 = __half22float2(*(__half2*)&u1.y);
        float2 a2 = __half22float2(*(__half2*)&u2.x);
        float2 b2 = __half22float2(*(__half2*)&u2.y);
        float2 a3 = __half22float2(*(__half2*)&u3.x);
        float2 b3 = __half22float2(*(__half2*)&u3.y);
        acc.x += a0.x * w0 + a1.x * w1 + a2.x * w2 + a3.x * w3;
        acc.y += a0.y * w0 + a1.y * w1 + a2.y * w2 + a3.y * w3;
        acc.z += b0.x * w0 + b1.x * w1 + b2.x * w2 + b3.x * w3;
        acc.w += b0.y * w0 + b1.y * w1 + b2.y * w2 + b3.y * w3;
    }
    for (; j < end; j++) {
        int2 e = epack[j];
        float w = __int_as_float(e.y);
        uint2 u = ((const uint2*)(H + (size_t)e.x * 128))[lane];
        float2 a = __half22float2(*(__half2*)&u.x);
        float2 b = __half22float2(*(__half2*)&u.y);
        acc.x += a.x * w; acc.y += a.y * w;
        acc.z += b.x * w; acc.w += b.y * w;
    }

    float4 b = ((const float4*)bias)[lane];
    acc.x = fmaxf(acc.x + b.x, 0.f);
    acc.y = fmaxf(acc.y + b.y, 0.f);
    acc.z = fmaxf(acc.z + b.z, 0.f);
    acc.w = fmaxf(acc.w + b.w, 0.f);
    ((float4*)(Y + (size_t)node * 128))[lane] = acc;
}

// D=40 gather (fp16 H) + bias + log_softmax, one warp per node.
__global__ void agg40_lsm_kernel(const int* __restrict__ rowptr,
                                 const int2* __restrict__ epack,
                                 const __half* __restrict__ H,
                                 const float* __restrict__ b,
                                 float* __restrict__ out, int n) {
    int node = blockIdx.x * 8 + (threadIdx.x >> 5);
    if (node >= n) return;
    const int lane = threadIdx.x & 31;
    int beg = rowptr[node];
    int end = rowptr[node + 1];

    float a0 = 0.f, a1 = 0.f;
    int j = beg;
    for (; j + 1 < end; j += 2) {
        int2 e0 = epack[j]; int2 e1 = epack[j + 1];
        float w0 = __int_as_float(e0.y), w1 = __int_as_float(e1.y);
        const __half* h0 = H + (size_t)e0.x * DO;
        const __half* h1 = H + (size_t)e1.x * DO;
        a0 += __half2float(h0[lane]) * w0 + __half2float(h1[lane]) * w1;
        if (lane < 8)
            a1 += __half2float(h0[32 + lane]) * w0
                + __half2float(h1[32 + lane]) * w1;
    }
    if (j < end) {
        int2 e = epack[j];
        float w = __int_as_float(e.y);
        const __half* hs = H + (size_t)e.x * DO;
        a0 += __half2float(hs[lane]) * w;
        if (lane < 8) a1 += __half2float(hs[32 + lane]) * w;
    }

    float v0 = a0 + b[lane];
    float v1 = (lane < 8) ? (a1 + b[32 + lane]) : -1e30f;

    float m = fmaxf(v0, v1);
#pragma unroll
    for (int o = 16; o; o >>= 1) m = fmaxf(m, __shfl_xor_sync(0xffffffffu, m, o));

    float sum = __expf(v0 - m) + ((lane < 8) ? __expf(v1 - m) : 0.f);
#pragma unroll
    for (int o = 16; o; o >>= 1) sum += __shfl_xor_sync(0xffffffffu, sum, o);

    float lse = m + __logf(sum);
    out[(size_t)node * DO + lane] = v0 - lse;
    if (lane < 8) out[(size_t)node * DO + 32 + lane] = v1 - lse;
}

// ---------------------------------------------------------------------------
extern "C" void kernel_launch(void* const* d_in, const int* in_sizes, int n_in,
                              void* d_out, int out_size) {
    const float* x  = (const float*)d_in[0];
    const void*  ei = d_in[1];
    const float* ew = (const float*)d_in[2];
    const float* W1 = (const float*)d_in[3];
    const float* b1 = (const float*)d_in[4];
    const float* W2 = (const float*)d_in[5];
    const float* b2 = (const float*)d_in[6];
    const float* W3 = (const float*)d_in[7];
    const float* b3 = (const float*)d_in[8];
    float* out = (float*)d_out;

    const int n  = in_sizes[0] / DH;
    int ne = in_sizes[1] / 2;
    if (ne > MAXE) ne = MAXE;
    (void)n_in; (void)out_size;

    float *A, *B;
    int *rowptr, *deg, *fill, *partials;
    int2* epack;
    __nv_bfloat16 *w1hi, *w1lo, *w2hi, *w2lo;
    cudaGetSymbolAddress((void**)&A, g_bufA);
    cudaGetSymbolAddress((void**)&B, g_bufB);
    cudaGetSymbolAddress((void**)&rowptr, g_rowptr);
    cudaGetSymbolAddress((void**)&deg, g_deg);
    cudaGetSymbolAddress((void**)&fill, g_fill);
    cudaGetSymbolAddress((void**)&epack, g_epack);
    cudaGetSymbolAddress((void**)&partials, g_partials);
    cudaGetSymbolAddress((void**)&w1hi, g_w1hi);
    cudaGetSymbolAddress((void**)&w1lo, g_w1lo);
    cudaGetSymbolAddress((void**)&w2hi, g_w2hi);
    cudaGetSymbolAddress((void**)&w2lo, g_w2lo);

    __half* Ah = (__half*)A;    // fp16 H buffer (reinterpreted scratch)

    const int SMEM_TC = (2 * 64 * LDX + 2 * 128 * LDW) * (int)sizeof(__nv_bfloat16);
    const int SMEM40  = (128 * DO + 64 * 128) * (int)sizeof(float);
    cudaFuncSetAttribute(gemm128_tc_kernel,
                         cudaFuncAttributeMaxDynamicSharedMemorySize, SMEM_TC);
    cudaFuncSetAttribute(gemm40_kernel,
                         cudaFuncAttributeMaxDynamicSharedMemorySize, SMEM40);

    const int tcBlocks       = (n + 63) / 64;
    const int nodeWarpBlocks = (n + 7) / 8;
    const int scanBlocks     = (n + 1023) / 1024;
    const int edge2Blocks    = ((ne + 1) / 2 + 255) / 256;

    static cudaStream_t s2 = nullptr;
    static cudaEvent_t evFork = nullptr, evJoin = nullptr;
    if (s2 == nullptr) {
        cudaStreamCreateWithFlags(&s2, cudaStreamNonBlocking);
        cudaEventCreateWithFlags(&evFork, cudaEventDisableTiming);
        cudaEventCreateWithFlags(&evJoin, cudaEventDisableTiming);
    }

    // ---- fork: CSR build on side stream ----
    cudaEventRecord(evFork, 0);
    cudaStreamWaitEvent(s2, evFork, 0);
    deg_zero_kernel<<<(n + 255) / 256, 256, 0, s2>>>(deg, n, ei, n);
    deg_count_kernel<<<edge2Blocks, 256, 0, s2>>>(ei, ne, deg);
    scan_block_kernel<<<scanBlocks, 1024, 0, s2>>>(deg, rowptr, partials, n);
    scan_partials_kernel<<<1, 128, 0, s2>>>(partials, scanBlocks);
    scan_add_kernel<<<(n + 255) / 256, 256, 0, s2>>>(rowptr, partials, fill, n, ne);
    csr_fill_kernel<<<edge2Blocks, 256, 0, s2>>>(ei, ew, ne, fill, epack);
    cudaEventRecord(evJoin, s2);

    // ---- main stream: W prep + layer-1 GEMM overlap the CSR build ----
    prep_w2_kernel<<<128, 256>>>(W1, w1hi, w1lo, W2, w2hi, w2lo);
    gemm128_tc_kernel<<<tcBlocks, 256, SMEM_TC>>>(x, w1hi, w1lo, Ah, n);

    // ---- join ----
    cudaStreamWaitEvent(0, evJoin, 0);

    // ---- layer 1 ----
    agg128_kernel<<<nodeWarpBlocks, 256>>>(rowptr, epack, Ah, b1, B, n);
    // ---- layer 2 ----
    gemm128_tc_kernel<<<tcBlocks, 256, SMEM_TC>>>(B, w2hi, w2lo, Ah, n);
    agg128_kernel<<<nodeWarpBlocks, 256>>>(rowptr, epack, Ah, b2, B, n);
    // ---- layer 3 (D_OUT = 40) ----
    gemm40_kernel<<<tcBlocks, 320, SMEM40>>>(B, W3, Ah, n);
    agg40_lsm_kernel<<<nodeWarpBlocks, 256>>>(rowptr, epack, Ah, b3, out, n);
}